// round 2
// baseline (speedup 1.0000x reference)
#include <cuda_runtime.h>
#include <cstddef>

// Problem constants
#define NTOK 4096
#define DDIM 1024

// ---------------------------------------------------------------------------
// Scratch (allocation-free: __device__ globals)
// ---------------------------------------------------------------------------
__device__ float g_Q[(size_t)NTOK * DDIM];          // 16 MB
__device__ float g_K[(size_t)NTOK * DDIM];          // 16 MB
__device__ float g_V[(size_t)NTOK * DDIM];          // 16 MB
__device__ float g_S[(size_t)NTOK * NTOK];          // 64 MB scores/probs

// ---------------------------------------------------------------------------
// 128x128x8 register-tiled fp32 GEMM, NT form: C[M,N] = scale * (A @ B^T) + bias
//   A: [M,K] row-major, B: [N,K] row-major (contract over K = innermost of both)
// 256 threads, 8x8 per-thread micro-tile in split layout:
//   thread (tx,ty) owns rows {ty*4..+3, 64+ty*4..+3} x cols {tx*4..+3, 64+tx*4..+3}
// Smem padded to 132 floats/row: conflict-free transpose stores and LDS.128 reads.
// ---------------------------------------------------------------------------
__global__ void __launch_bounds__(256) sgemm_nt(
    const float* __restrict__ A, const float* __restrict__ B,
    const float* __restrict__ bias, float* __restrict__ C,
    int M, int N, int K, float scale)
{
    __shared__ float As[8][132];
    __shared__ float Bs[8][132];

    const int tid = threadIdx.x;
    const int tx = tid & 15;        // 0..15
    const int ty = tid >> 4;        // 0..15

    const float* Ab = A + (size_t)(blockIdx.y * 128) * K;
    const float* Bb = B + (size_t)(blockIdx.x * 128) * K;

    const int lr = tid >> 1;        // 0..127 (tile row to load)
    const int lc = (tid & 1) * 4;   // 0 or 4 (k sub-offset)

    float acc[8][8];
#pragma unroll
    for (int i = 0; i < 8; i++)
#pragma unroll
        for (int j = 0; j < 8; j++) acc[i][j] = 0.f;

    // register prefetch of first tile
    float4 a_pf = *(const float4*)(Ab + (size_t)lr * K + lc);
    float4 b_pf = *(const float4*)(Bb + (size_t)lr * K + lc);

    for (int k0 = 0; k0 < K; k0 += 8) {
        // transpose-store into smem (pad 132 -> conflict-free)
        As[lc + 0][lr] = a_pf.x; As[lc + 1][lr] = a_pf.y;
        As[lc + 2][lr] = a_pf.z; As[lc + 3][lr] = a_pf.w;
        Bs[lc + 0][lr] = b_pf.x; Bs[lc + 1][lr] = b_pf.y;
        Bs[lc + 2][lr] = b_pf.z; Bs[lc + 3][lr] = b_pf.w;
        __syncthreads();

        if (k0 + 8 < K) {  // issue next-tile loads; latency hidden by compute
            a_pf = *(const float4*)(Ab + (size_t)lr * K + k0 + 8 + lc);
            b_pf = *(const float4*)(Bb + (size_t)lr * K + k0 + 8 + lc);
        }

#pragma unroll
        for (int kk = 0; kk < 8; kk++) {
            float4 a0 = *(const float4*)&As[kk][ty * 4];
            float4 a1 = *(const float4*)&As[kk][ty * 4 + 64];
            float4 b0 = *(const float4*)&Bs[kk][tx * 4];
            float4 b1 = *(const float4*)&Bs[kk][tx * 4 + 64];
            float ar[8] = {a0.x, a0.y, a0.z, a0.w, a1.x, a1.y, a1.z, a1.w};
            float br[8] = {b0.x, b0.y, b0.z, b0.w, b1.x, b1.y, b1.z, b1.w};
#pragma unroll
            for (int i = 0; i < 8; i++)
#pragma unroll
                for (int j = 0; j < 8; j++)
                    acc[i][j] += ar[i] * br[j];
        }
        __syncthreads();
    }

    // epilogue: scale + optional bias, float4 stores
    const int row0 = blockIdx.y * 128;
    const int col0 = blockIdx.x * 128;
#pragma unroll
    for (int i = 0; i < 8; i++) {
        int r = row0 + ((i < 4) ? (ty * 4 + i) : (64 + ty * 4 + (i - 4)));
#pragma unroll
        for (int jh = 0; jh < 2; jh++) {
            int c = col0 + tx * 4 + jh * 64;
            float4 v;
            v.x = acc[i][jh * 4 + 0] * scale;
            v.y = acc[i][jh * 4 + 1] * scale;
            v.z = acc[i][jh * 4 + 2] * scale;
            v.w = acc[i][jh * 4 + 3] * scale;
            if (bias) {
                float4 bv = *(const float4*)(bias + c);
                v.x += bv.x; v.y += bv.y; v.z += bv.z; v.w += bv.w;
            }
            *(float4*)(C + (size_t)r * N + c) = v;
        }
    }
}

// ---------------------------------------------------------------------------
// NN form: C[M,N] = A @ B   (A: [M,K] row-major, B: [K,N] row-major)
// Only the B-tile loader differs (direct copy, no transpose).
// ---------------------------------------------------------------------------
__global__ void __launch_bounds__(256) sgemm_nn(
    const float* __restrict__ A, const float* __restrict__ B,
    float* __restrict__ C, int M, int N, int K)
{
    __shared__ float As[8][132];
    __shared__ float Bs[8][132];

    const int tid = threadIdx.x;
    const int tx = tid & 15;
    const int ty = tid >> 4;

    const float* Ab = A + (size_t)(blockIdx.y * 128) * K;
    const float* Bb = B + blockIdx.x * 128;

    const int lr = tid >> 1;            // A loader: 0..127
    const int lc = (tid & 1) * 4;
    const int kb = tid >> 5;            // B loader: k row 0..7
    const int jc = (tid & 31) * 4;      // B loader: col 0..124

    float acc[8][8];
#pragma unroll
    for (int i = 0; i < 8; i++)
#pragma unroll
        for (int j = 0; j < 8; j++) acc[i][j] = 0.f;

    float4 a_pf = *(const float4*)(Ab + (size_t)lr * K + lc);
    float4 b_pf = *(const float4*)(Bb + (size_t)kb * N + jc);

    for (int k0 = 0; k0 < K; k0 += 8) {
        As[lc + 0][lr] = a_pf.x; As[lc + 1][lr] = a_pf.y;
        As[lc + 2][lr] = a_pf.z; As[lc + 3][lr] = a_pf.w;
        *(float4*)&Bs[kb][jc] = b_pf;
        __syncthreads();

        if (k0 + 8 < K) {
            a_pf = *(const float4*)(Ab + (size_t)lr * K + k0 + 8 + lc);
            b_pf = *(const float4*)(Bb + (size_t)(k0 + 8 + kb) * N + jc);
        }

#pragma unroll
        for (int kk = 0; kk < 8; kk++) {
            float4 a0 = *(const float4*)&As[kk][ty * 4];
            float4 a1 = *(const float4*)&As[kk][ty * 4 + 64];
            float4 b0 = *(const float4*)&Bs[kk][tx * 4];
            float4 b1 = *(const float4*)&Bs[kk][tx * 4 + 64];
            float ar[8] = {a0.x, a0.y, a0.z, a0.w, a1.x, a1.y, a1.z, a1.w};
            float br[8] = {b0.x, b0.y, b0.z, b0.w, b1.x, b1.y, b1.z, b1.w};
#pragma unroll
            for (int i = 0; i < 8; i++)
#pragma unroll
                for (int j = 0; j < 8; j++)
                    acc[i][j] += ar[i] * br[j];
        }
        __syncthreads();
    }

    const int row0 = blockIdx.y * 128;
    const int col0 = blockIdx.x * 128;
#pragma unroll
    for (int i = 0; i < 8; i++) {
        int r = row0 + ((i < 4) ? (ty * 4 + i) : (64 + ty * 4 + (i - 4)));
#pragma unroll
        for (int jh = 0; jh < 2; jh++) {
            int c = col0 + tx * 4 + jh * 64;
            float4 v;
            v.x = acc[i][jh * 4 + 0];
            v.y = acc[i][jh * 4 + 1];
            v.z = acc[i][jh * 4 + 2];
            v.w = acc[i][jh * 4 + 3];
            *(float4*)(C + (size_t)r * N + c) = v;
        }
    }
}

// ---------------------------------------------------------------------------
// Row softmax over g_S (4096 rows of 4096). One block per row; row staged in smem.
// ---------------------------------------------------------------------------
__global__ void __launch_bounds__(256) softmax_rows(float* __restrict__ S, int n)
{
    __shared__ float rowbuf[NTOK];   // 16 KB
    __shared__ float red[256];

    const int tid = threadIdx.x;
    float* Sr = S + (size_t)blockIdx.x * n;

    float m = -1e30f;
    for (int i = tid; i < n; i += 256) {
        float v = Sr[i];
        rowbuf[i] = v;
        m = fmaxf(m, v);
    }
    red[tid] = m;
    __syncthreads();
#pragma unroll
    for (int s = 128; s > 0; s >>= 1) {
        if (tid < s) red[tid] = fmaxf(red[tid], red[tid + s]);
        __syncthreads();
    }
    m = red[0];
    __syncthreads();

    float sum = 0.f;
    for (int i = tid; i < n; i += 256) {
        float e = __expf(rowbuf[i] - m);
        rowbuf[i] = e;
        sum += e;
    }
    red[tid] = sum;
    __syncthreads();
#pragma unroll
    for (int s = 128; s > 0; s >>= 1) {
        if (tid < s) red[tid] += red[tid + s];
        __syncthreads();
    }
    const float inv = 1.f / red[0];
    __syncthreads();

    for (int i = tid; i < n; i += 256)
        Sr[i] = rowbuf[i] * inv;
}

// ---------------------------------------------------------------------------
// Launch: 3x QKV NT-GEMM -> QK^T NT-GEMM (scale 1/32) -> softmax -> PV NN-GEMM
// ---------------------------------------------------------------------------
extern "C" void kernel_launch(void* const* d_in, const int* in_sizes, int n_in,
                              void* d_out, int out_size)
{
    const float* x  = (const float*)d_in[0];
    const float* Wq = (const float*)d_in[1];
    const float* bq = (const float*)d_in[2];
    const float* Wk = (const float*)d_in[3];
    const float* bk = (const float*)d_in[4];
    const float* Wv = (const float*)d_in[5];
    const float* bv = (const float*)d_in[6];
    float* out = (float*)d_out;

    float *Q, *K, *V, *S;
    cudaGetSymbolAddress((void**)&Q, g_Q);
    cudaGetSymbolAddress((void**)&K, g_K);
    cudaGetSymbolAddress((void**)&V, g_V);
    cudaGetSymbolAddress((void**)&S, g_S);

    dim3 blk(256);

    // QKV projections: [4096,1024] = x @ W^T + b
    dim3 gProj(DDIM / 128, NTOK / 128);
    sgemm_nt<<<gProj, blk>>>(x, Wq, bq, Q, NTOK, DDIM, DDIM, 1.0f);
    sgemm_nt<<<gProj, blk>>>(x, Wk, bk, K, NTOK, DDIM, DDIM, 1.0f);
    sgemm_nt<<<gProj, blk>>>(x, Wv, bv, V, NTOK, DDIM, DDIM, 1.0f);

    // Scores: S = (Q @ K^T) / sqrt(1024)
    dim3 gScore(NTOK / 128, NTOK / 128);
    sgemm_nt<<<gScore, blk>>>(Q, K, nullptr, S, NTOK, NTOK, DDIM, 0.03125f);

    // Row softmax
    softmax_rows<<<NTOK, blk>>>(S, NTOK);

    // Output: out = P @ V
    dim3 gOut(DDIM / 128, NTOK / 128);
    sgemm_nn<<<gOut, blk>>>(S, V, out, NTOK, DDIM, NTOK);
}

// round 6
// speedup vs baseline: 1.7286x; 1.7286x over previous
#include <cuda_runtime.h>
#include <cstdint>
#include <cstddef>

#define NTOK 4096
#define DDIM 1024

// ---------------------------------------------------------------------------
// Scratch (allocation-free)
// ---------------------------------------------------------------------------
__device__ float g_Q[(size_t)NTOK * DDIM];          // Q  [4096,1024]
__device__ float g_K[(size_t)NTOK * DDIM];          // K  [4096,1024]
__device__ float g_V[(size_t)DDIM * NTOK];          // V^T [1024,4096]
__device__ float g_S[(size_t)NTOK * NTOK];          // scores/probs [4096,4096]

// ---------------------------------------------------------------------------
// Helpers
// ---------------------------------------------------------------------------
__device__ __forceinline__ void cp16(uint32_t dst, const void* src) {
    asm volatile("cp.async.cg.shared.global [%0], [%1], 16;" :: "r"(dst), "l"(src) : "memory");
}
#define CP_COMMIT()  asm volatile("cp.async.commit_group;" ::: "memory")
#define CP_WAIT(n)   asm volatile("cp.async.wait_group %0;" :: "n"(n) : "memory")

__device__ __forceinline__ uint32_t smem_u32(const void* p) {
    uint32_t a;
    asm("{ .reg .u64 t; cvta.to.shared.u64 t, %1; cvt.u32.u64 %0, t; }" : "=r"(a) : "l"(p));
    return a;
}
__device__ __forceinline__ uint32_t f2tf32(float x) {
    uint32_t r;
    asm("cvt.rna.tf32.f32 %0, %1;" : "=r"(r) : "f"(x));
    return r;
}
__device__ __forceinline__ void mma_tf32(float c[4], const uint32_t a[4], const uint32_t b[2]) {
    asm volatile(
        "mma.sync.aligned.m16n8k8.row.col.f32.tf32.tf32.f32 "
        "{%0,%1,%2,%3}, {%4,%5,%6,%7}, {%8,%9}, {%0,%1,%2,%3};"
        : "+f"(c[0]), "+f"(c[1]), "+f"(c[2]), "+f"(c[3])
        : "r"(a[0]), "r"(a[1]), "r"(a[2]), "r"(a[3]), "r"(b[0]), "r"(b[1]));
}

// ---------------------------------------------------------------------------
// tf32 mma.sync NT-GEMM: C[M,N] = scale*(A @ B^T) + bias
//   A [M,K] row-major, B [N,K] row-major. M,N % 128 == 0, K % 32 == 0.
//   bias_mode: 0 = none, 1 = per-column bias[c], 2 = per-row bias[r]
//
// 256 threads (8 warps, 2x4 warp grid, 64x32 warp tile, m16n8k8 frags).
// 5-stage cp.async pipeline. Smem tiles [128][36] (pad -> conflict-free STS.128
// and conflict-free scalar frag LDS: bank = 4*(lane>>2) + lane%4).
// ---------------------------------------------------------------------------
#define STAGES 5
#define BK 32
#define TILE_W 36                               // padded row stride (words)
#define TILE_WORDS (128 * TILE_W)               // 4608 words per operand tile
#define STAGE_WORDS (2 * TILE_WORDS)            // 9216
#define GEMM_SMEM (STAGES * STAGE_WORDS * 4)    // 184320 bytes

__global__ void __launch_bounds__(256, 1)
gemm_tf32(const float* __restrict__ A, const float* __restrict__ B,
          const float* __restrict__ bias, float* __restrict__ C,
          int M, int N, int K, float scale, int bias_mode)
{
    extern __shared__ float smem[];
    const uint32_t sb = smem_u32(smem);

    const int tid  = threadIdx.x;
    const int wid  = tid >> 5;
    const int lane = tid & 31;
    const int r4   = lane >> 2;     // 0..7
    const int t4   = lane & 3;      // 0..3

    const int warpRow = (wid & 1) * 64;   // 2 warps over M
    const int warpCol = (wid >> 1) * 32;  // 4 warps over N

    const int row0 = blockIdx.y * 128;
    const int col0 = blockIdx.x * 128;
    const int NITER = K / BK;

    // loader mapping: thread t -> tile row t>>1, k offset (t&1)*16, 4 cp16 per operand
    const int lrow = tid >> 1;
    const int lk4  = (tid & 1) * 16;
    const float* Ag = A + (size_t)(row0 + lrow) * K + lk4;
    const float* Bg = B + (size_t)(col0 + lrow) * K + lk4;
    const uint32_t dstA = sb + (uint32_t)(lrow * TILE_W + lk4) * 4u;
    const uint32_t dstB = dstA + TILE_WORDS * 4u;

    float acc[4][4][4];
#pragma unroll
    for (int i = 0; i < 4; i++)
#pragma unroll
        for (int j = 0; j < 4; j++)
#pragma unroll
            for (int q = 0; q < 4; q++) acc[i][j][q] = 0.f;

    // --- prologue: fill STAGES-1 stages ---
#pragma unroll
    for (int p = 0; p < STAGES - 1; p++) {
        const uint32_t so = (uint32_t)(p * STAGE_WORDS) * 4u;
        const float* a = Ag + (size_t)p * BK;
        const float* b = Bg + (size_t)p * BK;
#pragma unroll
        for (int i = 0; i < 4; i++) {
            cp16(dstA + so + i * 16u, a + i * 4);
            cp16(dstB + so + i * 16u, b + i * 4);
        }
        CP_COMMIT();
    }

    // --- mainloop ---
    for (int j = 0; j < NITER; j++) {
        CP_WAIT(STAGES - 2);
        __syncthreads();   // stage j visible to all; all warps past iter j-1 reads

        // issue stage j+STAGES-1 into slot (j-1)%STAGES (just-freed buffer)
        const int jn = j + STAGES - 1;
        if (jn < NITER) {
            const uint32_t so = (uint32_t)((jn % STAGES) * STAGE_WORDS) * 4u;
            const float* a = Ag + (size_t)jn * BK;
            const float* b = Bg + (size_t)jn * BK;
#pragma unroll
            for (int i = 0; i < 4; i++) {
                cp16(dstA + so + i * 16u, a + i * 4);
                cp16(dstB + so + i * 16u, b + i * 4);
            }
            CP_COMMIT();
        }

        const float* as = smem + (j % STAGES) * STAGE_WORDS;
        const float* bs = as + TILE_WORDS;

#pragma unroll
        for (int kk = 0; kk < 4; kk++) {
            const int kb = kk * 8;
            uint32_t afr[4][4], bfr[4][2];
#pragma unroll
            for (int mf = 0; mf < 4; mf++) {
                const int r = warpRow + mf * 16 + r4;
                afr[mf][0] = f2tf32(as[r * TILE_W + kb + t4]);
                afr[mf][1] = f2tf32(as[(r + 8) * TILE_W + kb + t4]);
                afr[mf][2] = f2tf32(as[r * TILE_W + kb + 4 + t4]);
                afr[mf][3] = f2tf32(as[(r + 8) * TILE_W + kb + 4 + t4]);
            }
#pragma unroll
            for (int nf = 0; nf < 4; nf++) {
                const int n = warpCol + nf * 8 + r4;
                bfr[nf][0] = f2tf32(bs[n * TILE_W + kb + t4]);
                bfr[nf][1] = f2tf32(bs[n * TILE_W + kb + 4 + t4]);
            }
#pragma unroll
            for (int mf = 0; mf < 4; mf++)
#pragma unroll
                for (int nf = 0; nf < 4; nf++)
                    mma_tf32(acc[mf][nf], afr[mf], bfr[nf]);
        }
    }

    // --- epilogue ---
#pragma unroll
    for (int mf = 0; mf < 4; mf++) {
#pragma unroll
        for (int half = 0; half < 2; half++) {
            const int r = row0 + warpRow + mf * 16 + r4 + half * 8;
            const float brow = (bias_mode == 2) ? bias[r] : 0.f;
            float* Crow = C + (size_t)r * N + col0;
#pragma unroll
            for (int nf = 0; nf < 4; nf++) {
                const int c = warpCol + nf * 8 + 2 * t4;
                float2 v;
                v.x = acc[mf][nf][half * 2 + 0] * scale;
                v.y = acc[mf][nf][half * 2 + 1] * scale;
                if (bias_mode == 1) {
                    v.x += bias[col0 + c];
                    v.y += bias[col0 + c + 1];
                } else {
                    v.x += brow;
                    v.y += brow;
                }
                *(float2*)(Crow + c) = v;
            }
        }
    }
}

// ---------------------------------------------------------------------------
// Row softmax over g_S (4096 rows of 4096)
// ---------------------------------------------------------------------------
__global__ void __launch_bounds__(256) softmax_rows(float* __restrict__ S, int n)
{
    __shared__ float rowbuf[NTOK];
    __shared__ float red[256];

    const int tid = threadIdx.x;
    float* Sr = S + (size_t)blockIdx.x * n;

    float m = -1e30f;
    for (int i = tid; i < n; i += 256) {
        float v = Sr[i];
        rowbuf[i] = v;
        m = fmaxf(m, v);
    }
    red[tid] = m;
    __syncthreads();
#pragma unroll
    for (int s = 128; s > 0; s >>= 1) {
        if (tid < s) red[tid] = fmaxf(red[tid], red[tid + s]);
        __syncthreads();
    }
    m = red[0];
    __syncthreads();

    float sum = 0.f;
    for (int i = tid; i < n; i += 256) {
        float e = __expf(rowbuf[i] - m);
        rowbuf[i] = e;
        sum += e;
    }
    red[tid] = sum;
    __syncthreads();
#pragma unroll
    for (int s = 128; s > 0; s >>= 1) {
        if (tid < s) red[tid] += red[tid + s];
        __syncthreads();
    }
    const float inv = 1.f / red[0];
    __syncthreads();

    for (int i = tid; i < n; i += 256)
        Sr[i] = rowbuf[i] * inv;
}

// ---------------------------------------------------------------------------
// Launch graph:
//   Q  = x @ Wq^T + bq          (col bias)
//   K  = x @ Wk^T + bk          (col bias)
//   Vt = Wv @ x^T + bv          (row bias)   -> V^T [1024,4096]
//   S  = (Q @ K^T) / 32
//   P  = softmax_rows(S)
//   out = P @ Vt^T
// ---------------------------------------------------------------------------
extern "C" void kernel_launch(void* const* d_in, const int* in_sizes, int n_in,
                              void* d_out, int out_size)
{
    const float* x  = (const float*)d_in[0];
    const float* Wq = (const float*)d_in[1];
    const float* bq = (const float*)d_in[2];
    const float* Wk = (const float*)d_in[3];
    const float* bk = (const float*)d_in[4];
    const float* Wv = (const float*)d_in[5];
    const float* bv = (const float*)d_in[6];
    float* out = (float*)d_out;

    float *Q, *K, *Vt, *S;
    cudaGetSymbolAddress((void**)&Q,  g_Q);
    cudaGetSymbolAddress((void**)&K,  g_K);
    cudaGetSymbolAddress((void**)&Vt, g_V);
    cudaGetSymbolAddress((void**)&S,  g_S);

    cudaFuncSetAttribute(gemm_tf32, cudaFuncAttributeMaxDynamicSharedMemorySize, GEMM_SMEM);

    dim3 blk(256);

    // Projections
    gemm_tf32<<<dim3(DDIM / 128, NTOK / 128), blk, GEMM_SMEM>>>(x, Wq, bq, Q, NTOK, DDIM, DDIM, 1.0f, 1);
    gemm_tf32<<<dim3(DDIM / 128, NTOK / 128), blk, GEMM_SMEM>>>(x, Wk, bk, K, NTOK, DDIM, DDIM, 1.0f, 1);
    gemm_tf32<<<dim3(NTOK / 128, DDIM / 128), blk, GEMM_SMEM>>>(Wv, x, bv, Vt, DDIM, NTOK, DDIM, 1.0f, 2);

    // Scores
    gemm_tf32<<<dim3(NTOK / 128, NTOK / 128), blk, GEMM_SMEM>>>(Q, K, nullptr, S, NTOK, NTOK, DDIM, 0.03125f, 0);

    // Softmax
    softmax_rows<<<NTOK, blk>>>(S, NTOK);

    // Output
    gemm_tf32<<<dim3(DDIM / 128, NTOK / 128), blk, GEMM_SMEM>>>(S, Vt, nullptr, out, NTOK, DDIM, NTOK, 1.0f, 0);
}

// round 7
// speedup vs baseline: 1.8865x; 1.0914x over previous
#include <cuda_runtime.h>
#include <cstdint>
#include <cstddef>

#define NTOK 4096
#define DDIM 1024

// ---------------------------------------------------------------------------
// Scratch (allocation-free)
// ---------------------------------------------------------------------------
__device__ float g_Q[(size_t)NTOK * DDIM];          // Q  [4096,1024]
__device__ float g_K[(size_t)NTOK * DDIM];          // K  [4096,1024]
__device__ float g_V[(size_t)DDIM * NTOK];          // V^T [1024,4096]
__device__ float g_S[(size_t)NTOK * NTOK];          // scores/probs [4096,4096]

// ---------------------------------------------------------------------------
// Helpers
// ---------------------------------------------------------------------------
__device__ __forceinline__ void cp16(uint32_t dst, const void* src) {
    asm volatile("cp.async.cg.shared.global [%0], [%1], 16;" :: "r"(dst), "l"(src) : "memory");
}
#define CP_COMMIT()  asm volatile("cp.async.commit_group;" ::: "memory")
#define CP_WAIT(n)   asm volatile("cp.async.wait_group %0;" :: "n"(n) : "memory")

__device__ __forceinline__ uint32_t smem_u32(const void* p) {
    uint32_t a;
    asm("{ .reg .u64 t; cvta.to.shared.u64 t, %1; cvt.u32.u64 %0, t; }" : "=r"(a) : "l"(p));
    return a;
}
__device__ __forceinline__ uint32_t f2tf32(float x) {
    uint32_t r;
    asm("cvt.rna.tf32.f32 %0, %1;" : "=r"(r) : "f"(x));
    return r;
}
__device__ __forceinline__ void mma_tf32(float c[4], const uint32_t a[4], const uint32_t b[2]) {
    asm volatile(
        "mma.sync.aligned.m16n8k8.row.col.f32.tf32.tf32.f32 "
        "{%0,%1,%2,%3}, {%4,%5,%6,%7}, {%8,%9}, {%0,%1,%2,%3};"
        : "+f"(c[0]), "+f"(c[1]), "+f"(c[2]), "+f"(c[3])
        : "r"(a[0]), "r"(a[1]), "r"(a[2]), "r"(a[3]), "r"(b[0]), "r"(b[1]));
}

// ---------------------------------------------------------------------------
// tf32 mma.sync NT-GEMM: C[M,N] = scale*(A @ B^T) + bias
//   A [M,K] row-major, B [N,K] row-major. M,N % 128 == 0, K % 32 == 0.
//   bias_mode: 0 = none, 1 = per-column bias[c], 2 = per-row bias[r]
//
// 256 threads (8 warps, 2x4 warp grid, 64x32 warp tile, m16n8k8 frags).
// 3-stage cp.async pipeline, 110.6 KB smem -> 2 CTAs/SM (the round-6 change:
// co-resident CTA fills barrier/LDS-latency stalls; occ 12.4% -> 25%).
// Smem tiles [128][36] (pad -> conflict-free STS.128 and conflict-free scalar
// frag LDS: bank = 4*(lane>>2) + lane%4).
// ---------------------------------------------------------------------------
#define STAGES 3
#define BK 32
#define TILE_W 36                               // padded row stride (words)
#define TILE_WORDS (128 * TILE_W)               // 4608 words per operand tile
#define STAGE_WORDS (2 * TILE_WORDS)            // 9216
#define GEMM_SMEM (STAGES * STAGE_WORDS * 4)    // 110592 bytes

__global__ void __launch_bounds__(256, 2)
gemm_tf32(const float* __restrict__ A, const float* __restrict__ B,
          const float* __restrict__ bias, float* __restrict__ C,
          int M, int N, int K, float scale, int bias_mode)
{
    extern __shared__ float smem[];
    const uint32_t sb = smem_u32(smem);

    const int tid  = threadIdx.x;
    const int wid  = tid >> 5;
    const int lane = tid & 31;
    const int r4   = lane >> 2;     // 0..7
    const int t4   = lane & 3;      // 0..3

    const int warpRow = (wid & 1) * 64;   // 2 warps over M
    const int warpCol = (wid >> 1) * 32;  // 4 warps over N

    const int row0 = blockIdx.y * 128;
    const int col0 = blockIdx.x * 128;
    const int NITER = K / BK;

    // loader mapping: thread t -> tile row t>>1, k offset (t&1)*16, 4 cp16 per operand
    const int lrow = tid >> 1;
    const int lk4  = (tid & 1) * 16;
    const float* Ag = A + (size_t)(row0 + lrow) * K + lk4;
    const float* Bg = B + (size_t)(col0 + lrow) * K + lk4;
    const uint32_t dstA = sb + (uint32_t)(lrow * TILE_W + lk4) * 4u;
    const uint32_t dstB = dstA + TILE_WORDS * 4u;

    float acc[4][4][4];
#pragma unroll
    for (int i = 0; i < 4; i++)
#pragma unroll
        for (int j = 0; j < 4; j++)
#pragma unroll
            for (int q = 0; q < 4; q++) acc[i][j][q] = 0.f;

    // --- prologue: fill STAGES-1 stages ---
#pragma unroll
    for (int p = 0; p < STAGES - 1; p++) {
        const uint32_t so = (uint32_t)(p * STAGE_WORDS) * 4u;
        const float* a = Ag + (size_t)p * BK;
        const float* b = Bg + (size_t)p * BK;
#pragma unroll
        for (int i = 0; i < 4; i++) {
            cp16(dstA + so + i * 16u, a + i * 4);
            cp16(dstB + so + i * 16u, b + i * 4);
        }
        CP_COMMIT();
    }

    // --- mainloop ---
    for (int j = 0; j < NITER; j++) {
        CP_WAIT(STAGES - 2);
        __syncthreads();   // stage j visible to all; all warps past iter j-1 reads

        // issue stage j+STAGES-1 into the just-freed buffer
        const int jn = j + STAGES - 1;
        if (jn < NITER) {
            const uint32_t so = (uint32_t)((jn % STAGES) * STAGE_WORDS) * 4u;
            const float* a = Ag + (size_t)jn * BK;
            const float* b = Bg + (size_t)jn * BK;
#pragma unroll
            for (int i = 0; i < 4; i++) {
                cp16(dstA + so + i * 16u, a + i * 4);
                cp16(dstB + so + i * 16u, b + i * 4);
            }
            CP_COMMIT();
        }

        const float* as = smem + (j % STAGES) * STAGE_WORDS;
        const float* bs = as + TILE_WORDS;

#pragma unroll
        for (int kk = 0; kk < 4; kk++) {
            const int kb = kk * 8;
            uint32_t afr[4][4], bfr[4][2];
#pragma unroll
            for (int mf = 0; mf < 4; mf++) {
                const int r = warpRow + mf * 16 + r4;
                afr[mf][0] = f2tf32(as[r * TILE_W + kb + t4]);
                afr[mf][1] = f2tf32(as[(r + 8) * TILE_W + kb + t4]);
                afr[mf][2] = f2tf32(as[r * TILE_W + kb + 4 + t4]);
                afr[mf][3] = f2tf32(as[(r + 8) * TILE_W + kb + 4 + t4]);
            }
#pragma unroll
            for (int nf = 0; nf < 4; nf++) {
                const int n = warpCol + nf * 8 + r4;
                bfr[nf][0] = f2tf32(bs[n * TILE_W + kb + t4]);
                bfr[nf][1] = f2tf32(bs[n * TILE_W + kb + 4 + t4]);
            }
#pragma unroll
            for (int mf = 0; mf < 4; mf++)
#pragma unroll
                for (int nf = 0; nf < 4; nf++)
                    mma_tf32(acc[mf][nf], afr[mf], bfr[nf]);
        }
    }

    // --- epilogue ---
#pragma unroll
    for (int mf = 0; mf < 4; mf++) {
#pragma unroll
        for (int half = 0; half < 2; half++) {
            const int r = row0 + warpRow + mf * 16 + r4 + half * 8;
            const float brow = (bias_mode == 2) ? bias[r] : 0.f;
            float* Crow = C + (size_t)r * N + col0;
#pragma unroll
            for (int nf = 0; nf < 4; nf++) {
                const int c = warpCol + nf * 8 + 2 * t4;
                float2 v;
                v.x = acc[mf][nf][half * 2 + 0] * scale;
                v.y = acc[mf][nf][half * 2 + 1] * scale;
                if (bias_mode == 1) {
                    v.x += bias[col0 + c];
                    v.y += bias[col0 + c + 1];
                } else {
                    v.x += brow;
                    v.y += brow;
                }
                *(float2*)(Crow + c) = v;
            }
        }
    }
}

// ---------------------------------------------------------------------------
// Row softmax over g_S (4096 rows of 4096)
// ---------------------------------------------------------------------------
__global__ void __launch_bounds__(256) softmax_rows(float* __restrict__ S, int n)
{
    __shared__ float rowbuf[NTOK];
    __shared__ float red[256];

    const int tid = threadIdx.x;
    float* Sr = S + (size_t)blockIdx.x * n;

    float m = -1e30f;
    for (int i = tid; i < n; i += 256) {
        float v = Sr[i];
        rowbuf[i] = v;
        m = fmaxf(m, v);
    }
    red[tid] = m;
    __syncthreads();
#pragma unroll
    for (int s = 128; s > 0; s >>= 1) {
        if (tid < s) red[tid] = fmaxf(red[tid], red[tid + s]);
        __syncthreads();
    }
    m = red[0];
    __syncthreads();

    float sum = 0.f;
    for (int i = tid; i < n; i += 256) {
        float e = __expf(rowbuf[i] - m);
        rowbuf[i] = e;
        sum += e;
    }
    red[tid] = sum;
    __syncthreads();
#pragma unroll
    for (int s = 128; s > 0; s >>= 1) {
        if (tid < s) red[tid] += red[tid + s];
        __syncthreads();
    }
    const float inv = 1.f / red[0];
    __syncthreads();

    for (int i = tid; i < n; i += 256)
        Sr[i] = rowbuf[i] * inv;
}

// ---------------------------------------------------------------------------
// Launch graph:
//   Q  = x @ Wq^T + bq          (col bias)
//   K  = x @ Wk^T + bk          (col bias)
//   Vt = Wv @ x^T + bv          (row bias)   -> V^T [1024,4096]
//   S  = (Q @ K^T) / 32
//   P  = softmax_rows(S)
//   out = P @ Vt^T
// ---------------------------------------------------------------------------
extern "C" void kernel_launch(void* const* d_in, const int* in_sizes, int n_in,
                              void* d_out, int out_size)
{
    const float* x  = (const float*)d_in[0];
    const float* Wq = (const float*)d_in[1];
    const float* bq = (const float*)d_in[2];
    const float* Wk = (const float*)d_in[3];
    const float* bk = (const float*)d_in[4];
    const float* Wv = (const float*)d_in[5];
    const float* bv = (const float*)d_in[6];
    float* out = (float*)d_out;

    float *Q, *K, *Vt, *S;
    cudaGetSymbolAddress((void**)&Q,  g_Q);
    cudaGetSymbolAddress((void**)&K,  g_K);
    cudaGetSymbolAddress((void**)&Vt, g_V);
    cudaGetSymbolAddress((void**)&S,  g_S);

    cudaFuncSetAttribute(gemm_tf32, cudaFuncAttributeMaxDynamicSharedMemorySize, GEMM_SMEM);

    dim3 blk(256);

    // Projections
    gemm_tf32<<<dim3(DDIM / 128, NTOK / 128), blk, GEMM_SMEM>>>(x, Wq, bq, Q, NTOK, DDIM, DDIM, 1.0f, 1);
    gemm_tf32<<<dim3(DDIM / 128, NTOK / 128), blk, GEMM_SMEM>>>(x, Wk, bk, K, NTOK, DDIM, DDIM, 1.0f, 1);
    gemm_tf32<<<dim3(NTOK / 128, DDIM / 128), blk, GEMM_SMEM>>>(Wv, x, bv, Vt, DDIM, NTOK, DDIM, 1.0f, 2);

    // Scores
    gemm_tf32<<<dim3(NTOK / 128, NTOK / 128), blk, GEMM_SMEM>>>(Q, K, nullptr, S, NTOK, NTOK, DDIM, 0.03125f, 0);

    // Softmax
    softmax_rows<<<NTOK, blk>>>(S, NTOK);

    // Output
    gemm_tf32<<<dim3(DDIM / 128, NTOK / 128), blk, GEMM_SMEM>>>(S, Vt, nullptr, out, NTOK, DDIM, NTOK, 1.0f, 0);
}

// round 10
// speedup vs baseline: 2.2722x; 1.2044x over previous
#include <cuda_runtime.h>
#include <cstdint>
#include <cstddef>

#define NTOK 4096
#define DDIM 1024

// ---------------------------------------------------------------------------
// Scratch (allocation-free)
// ---------------------------------------------------------------------------
__device__ float g_Q[(size_t)NTOK * DDIM];          // Q  [4096,1024] (tf32-rounded)
__device__ float g_K[(size_t)NTOK * DDIM];          // K  [4096,1024] (tf32-rounded)
__device__ float g_V[(size_t)DDIM * NTOK];          // V^T [1024,4096] (tf32-rounded)
__device__ float g_S[(size_t)NTOK * NTOK];          // scores -> probs (probs tf32-rounded)
__device__ float g_Xr[(size_t)NTOK * DDIM];         // x rounded to tf32
__device__ float g_Wqr[(size_t)DDIM * DDIM];
__device__ float g_Wkr[(size_t)DDIM * DDIM];
__device__ float g_Wvr[(size_t)DDIM * DDIM];

// ---------------------------------------------------------------------------
// Helpers
// ---------------------------------------------------------------------------
__device__ __forceinline__ void cp16(uint32_t dst, const void* src) {
    asm volatile("cp.async.cg.shared.global [%0], [%1], 16;" :: "r"(dst), "l"(src) : "memory");
}
#define CP_COMMIT()  asm volatile("cp.async.commit_group;" ::: "memory")
#define CP_WAIT(n)   asm volatile("cp.async.wait_group %0;" :: "n"(n) : "memory")

__device__ __forceinline__ uint32_t smem_u32(const void* p) {
    uint32_t a;
    asm("{ .reg .u64 t; cvta.to.shared.u64 t, %1; cvt.u32.u64 %0, t; }" : "=r"(a) : "l"(p));
    return a;
}
__device__ __forceinline__ float tf32r(float x) {          // rna round to tf32
    uint32_t r;
    asm("cvt.rna.tf32.f32 %0, %1;" : "=r"(r) : "f"(x));
    return __uint_as_float(r);
}
__device__ __forceinline__ void mma_tf32(float c[4], const uint32_t a[4], const uint32_t* b) {
    asm volatile(
        "mma.sync.aligned.m16n8k8.row.col.f32.tf32.tf32.f32 "
        "{%0,%1,%2,%3}, {%4,%5,%6,%7}, {%8,%9}, {%0,%1,%2,%3};"
        : "+f"(c[0]), "+f"(c[1]), "+f"(c[2]), "+f"(c[3])
        : "r"(a[0]), "r"(a[1]), "r"(a[2]), "r"(a[3]), "r"(b[0]), "r"(b[1]));
}
#define LDSM_X4(r, addr) \
    asm volatile("ldmatrix.sync.aligned.m8n8.x4.shared.b16 {%0,%1,%2,%3}, [%4];" \
        : "=r"((r)[0]), "=r"((r)[1]), "=r"((r)[2]), "=r"((r)[3]) : "r"(addr))

// ---------------------------------------------------------------------------
// tf32 mma.sync NT-GEMM: C[M,N] = scale*(A @ B^T) + bias
//   A [M,K] row-major, B [N,K] row-major, both PRE-ROUNDED to tf32 bits.
//   bias_mode: 0 = none, 1 = per-column bias[c], 2 = per-row bias[r]
//   round_out: 1 -> round stored values to tf32 (for intermediates fed to MMA)
//
// 256 threads (8 warps, 2x4 warp grid, 64x32 warp tile, m16n8k8 frags).
// 3-stage cp.async pipeline (110.6 KB smem -> 2 CTAs/SM).
// Fragments via ldmatrix.x4 (6 per k-step instead of 24 scalar LDS), no cvt
// in mainloop. Smem tiles [128][36]: row stride 144B = 16 mod 128 ->
// LDSM phases conflict-free; cp.async STS.128 conflict-free.
// ---------------------------------------------------------------------------
#define STAGES 3
#define BK 32
#define TILE_W 36
#define TILE_WORDS (128 * TILE_W)               // 4608 words per operand tile
#define STAGE_WORDS (2 * TILE_WORDS)            // 9216
#define GEMM_SMEM (STAGES * STAGE_WORDS * 4)    // 110592 bytes

__global__ void __launch_bounds__(256, 2)
gemm_tf32(const float* __restrict__ A, const float* __restrict__ B,
          const float* __restrict__ bias, float* __restrict__ C,
          int M, int N, int K, float scale, int bias_mode, int round_out)
{
    extern __shared__ float smem[];
    const uint32_t sb = smem_u32(smem);

    const int tid  = threadIdx.x;
    const int wid  = tid >> 5;
    const int lane = tid & 31;
    const int r4   = lane >> 2;
    const int t4   = lane & 3;

    const int warpRow = (wid & 1) * 64;   // 2 warps over M
    const int warpCol = (wid >> 1) * 32;  // 4 warps over N

    const int row0 = blockIdx.y * 128;
    const int col0 = blockIdx.x * 128;
    const int NITER = K / BK;

    // ldmatrix per-lane base addresses (stage 0, kb = 0)
    // A: matrices {rows+0 @k, rows+8 @k, rows+0 @k+4, rows+8 @k+4}
    const int aRow = warpRow + (lane & 15);
    const int aCol = (lane >> 4) * 4;
    const uint32_t aAddr0 = sb + (uint32_t)(aRow * TILE_W + aCol) * 4u;
    // B: matrices {nf rows @k, nf rows @k+4, nf+1 rows @k, nf+1 rows @k+4}
    const int bRow = warpCol + ((lane >> 4) & 1) * 8 + (lane & 7);
    const int bCol = ((lane >> 3) & 1) * 4;
    const uint32_t bAddr0 = sb + (uint32_t)TILE_WORDS * 4u + (uint32_t)(bRow * TILE_W + bCol) * 4u;

    // loader mapping: thread t -> tile row t>>1, k offset (t&1)*16, 4 cp16/operand
    const int lrow = tid >> 1;
    const int lk4  = (tid & 1) * 16;
    const float* Ag = A + (size_t)(row0 + lrow) * K + lk4;
    const float* Bg = B + (size_t)(col0 + lrow) * K + lk4;
    const uint32_t dstA = sb + (uint32_t)(lrow * TILE_W + lk4) * 4u;
    const uint32_t dstB = dstA + TILE_WORDS * 4u;

    float acc[4][4][4];
#pragma unroll
    for (int i = 0; i < 4; i++)
#pragma unroll
        for (int j = 0; j < 4; j++)
#pragma unroll
            for (int q = 0; q < 4; q++) acc[i][j][q] = 0.f;

    // --- prologue ---
#pragma unroll
    for (int p = 0; p < STAGES - 1; p++) {
        const uint32_t so = (uint32_t)(p * STAGE_WORDS) * 4u;
        const float* a = Ag + (size_t)p * BK;
        const float* b = Bg + (size_t)p * BK;
#pragma unroll
        for (int i = 0; i < 4; i++) {
            cp16(dstA + so + i * 16u, a + i * 4);
            cp16(dstB + so + i * 16u, b + i * 4);
        }
        CP_COMMIT();
    }

    // --- mainloop ---
    for (int j = 0; j < NITER; j++) {
        CP_WAIT(STAGES - 2);
        __syncthreads();

        const int jn = j + STAGES - 1;
        if (jn < NITER) {
            const uint32_t so = (uint32_t)((jn % STAGES) * STAGE_WORDS) * 4u;
            const float* a = Ag + (size_t)jn * BK;
            const float* b = Bg + (size_t)jn * BK;
#pragma unroll
            for (int i = 0; i < 4; i++) {
                cp16(dstA + so + i * 16u, a + i * 4);
                cp16(dstB + so + i * 16u, b + i * 4);
            }
            CP_COMMIT();
        }

        const uint32_t so = (uint32_t)((j % STAGES) * STAGE_WORDS) * 4u;

#pragma unroll
        for (int kk = 0; kk < 4; kk++) {
            const uint32_t ko = (uint32_t)kk * 32u;      // 8 words per kk
            uint32_t afr[4][4], bfr[2][4];
#pragma unroll
            for (int mf = 0; mf < 4; mf++)
                LDSM_X4(afr[mf], aAddr0 + so + (uint32_t)(mf * 16 * TILE_W) * 4u + ko);
#pragma unroll
            for (int p = 0; p < 2; p++)
                LDSM_X4(bfr[p], bAddr0 + so + (uint32_t)(p * 16 * TILE_W) * 4u + ko);
#pragma unroll
            for (int mf = 0; mf < 4; mf++)
#pragma unroll
                for (int nf = 0; nf < 4; nf++)
                    mma_tf32(acc[mf][nf], afr[mf], &bfr[nf >> 1][(nf & 1) * 2]);
        }
    }

    // --- epilogue ---
#pragma unroll
    for (int mf = 0; mf < 4; mf++) {
#pragma unroll
        for (int half = 0; half < 2; half++) {
            const int r = row0 + warpRow + mf * 16 + r4 + half * 8;
            const float brow = (bias_mode == 2) ? bias[r] : 0.f;
            float* Crow = C + (size_t)r * N + col0;
#pragma unroll
            for (int nf = 0; nf < 4; nf++) {
                const int c = warpCol + nf * 8 + 2 * t4;
                float2 v;
                v.x = acc[mf][nf][half * 2 + 0] * scale;
                v.y = acc[mf][nf][half * 2 + 1] * scale;
                if (bias_mode == 1) {
                    v.x += bias[col0 + c];
                    v.y += bias[col0 + c + 1];
                } else {
                    v.x += brow;
                    v.y += brow;
                }
                if (round_out) { v.x = tf32r(v.x); v.y = tf32r(v.y); }
                *(float2*)(Crow + c) = v;
            }
        }
    }
}

// ---------------------------------------------------------------------------
// Elementwise tf32 rounding pass (src -> dst), float4 grid-stride
// ---------------------------------------------------------------------------
__global__ void __launch_bounds__(256) round_tf32_kernel(
    const float* __restrict__ src, float* __restrict__ dst, int n4)
{
    const float4* s4 = (const float4*)src;
    float4* d4 = (float4*)dst;
    for (int i = blockIdx.x * blockDim.x + threadIdx.x; i < n4; i += gridDim.x * blockDim.x) {
        float4 v = s4[i];
        v.x = tf32r(v.x); v.y = tf32r(v.y); v.z = tf32r(v.z); v.w = tf32r(v.w);
        d4[i] = v;
    }
}

// ---------------------------------------------------------------------------
// Row softmax over g_S; output rounded to tf32 (it feeds the PV MMA)
// ---------------------------------------------------------------------------
__global__ void __launch_bounds__(256) softmax_rows(float* __restrict__ S, int n)
{
    __shared__ float rowbuf[NTOK];
    __shared__ float red[256];

    const int tid = threadIdx.x;
    float* Sr = S + (size_t)blockIdx.x * n;

    float m = -1e30f;
    for (int i = tid; i < n; i += 256) {
        float v = Sr[i];
        rowbuf[i] = v;
        m = fmaxf(m, v);
    }
    red[tid] = m;
    __syncthreads();
#pragma unroll
    for (int s = 128; s > 0; s >>= 1) {
        if (tid < s) red[tid] = fmaxf(red[tid], red[tid + s]);
        __syncthreads();
    }
    m = red[0];
    __syncthreads();

    float sum = 0.f;
    for (int i = tid; i < n; i += 256) {
        float e = __expf(rowbuf[i] - m);
        rowbuf[i] = e;
        sum += e;
    }
    red[tid] = sum;
    __syncthreads();
#pragma unroll
    for (int s = 128; s > 0; s >>= 1) {
        if (tid < s) red[tid] += red[tid + s];
        __syncthreads();
    }
    const float inv = 1.f / red[0];
    __syncthreads();

    for (int i = tid; i < n; i += 256)
        Sr[i] = tf32r(rowbuf[i] * inv);
}

// ---------------------------------------------------------------------------
// Launch graph:
//   xr,Wr = tf32-round(x, Wq, Wk, Wv)
//   Q  = xr @ Wqr^T + bq   (col bias, rounded)
//   K  = xr @ Wkr^T + bk   (col bias, rounded)
//   Vt = Wvr @ xr^T + bv   (row bias, rounded)  -> V^T [1024,4096]
//   S  = (Q @ K^T) / 32    (not rounded)
//   P  = softmax_rows(S)   (rounded)
//   out = P @ Vt^T         (full precision store)
// ---------------------------------------------------------------------------
extern "C" void kernel_launch(void* const* d_in, const int* in_sizes, int n_in,
                              void* d_out, int out_size)
{
    const float* x  = (const float*)d_in[0];
    const float* Wq = (const float*)d_in[1];
    const float* bq = (const float*)d_in[2];
    const float* Wk = (const float*)d_in[3];
    const float* bk = (const float*)d_in[4];
    const float* Wv = (const float*)d_in[5];
    const float* bv = (const float*)d_in[6];
    float* out = (float*)d_out;

    float *Q, *K, *Vt, *S, *Xr, *Wqr, *Wkr, *Wvr;
    cudaGetSymbolAddress((void**)&Q,   g_Q);
    cudaGetSymbolAddress((void**)&K,   g_K);
    cudaGetSymbolAddress((void**)&Vt,  g_V);
    cudaGetSymbolAddress((void**)&S,   g_S);
    cudaGetSymbolAddress((void**)&Xr,  g_Xr);
    cudaGetSymbolAddress((void**)&Wqr, g_Wqr);
    cudaGetSymbolAddress((void**)&Wkr, g_Wkr);
    cudaGetSymbolAddress((void**)&Wvr, g_Wvr);

    cudaFuncSetAttribute(gemm_tf32, cudaFuncAttributeMaxDynamicSharedMemorySize, GEMM_SMEM);

    dim3 blk(256);

    // Pre-round inputs to tf32
    round_tf32_kernel<<<1024, blk>>>(x,  Xr,  NTOK * DDIM / 4);
    round_tf32_kernel<<<512,  blk>>>(Wq, Wqr, DDIM * DDIM / 4);
    round_tf32_kernel<<<512,  blk>>>(Wk, Wkr, DDIM * DDIM / 4);
    round_tf32_kernel<<<512,  blk>>>(Wv, Wvr, DDIM * DDIM / 4);

    // Projections (outputs rounded)
    gemm_tf32<<<dim3(DDIM / 128, NTOK / 128), blk, GEMM_SMEM>>>(Xr, Wqr, bq, Q, NTOK, DDIM, DDIM, 1.0f, 1, 1);
    gemm_tf32<<<dim3(DDIM / 128, NTOK / 128), blk, GEMM_SMEM>>>(Xr, Wkr, bk, K, NTOK, DDIM, DDIM, 1.0f, 1, 1);
    gemm_tf32<<<dim3(NTOK / 128, DDIM / 128), blk, GEMM_SMEM>>>(Wvr, Xr, bv, Vt, DDIM, NTOK, DDIM, 1.0f, 2, 1);

    // Scores
    gemm_tf32<<<dim3(NTOK / 128, NTOK / 128), blk, GEMM_SMEM>>>(Q, K, nullptr, S, NTOK, NTOK, DDIM, 0.03125f, 0, 0);

    // Softmax (output rounded)
    softmax_rows<<<NTOK, blk>>>(S, NTOK);

    // Output (full precision)
    gemm_tf32<<<dim3(DDIM / 128, NTOK / 128), blk, GEMM_SMEM>>>(S, Vt, nullptr, out, NTOK, DDIM, NTOK, 1.0f, 0, 0);
}

// round 11
// speedup vs baseline: 4.5585x; 2.0062x over previous
#include <cuda_runtime.h>
#include <cuda_fp16.h>
#include <cstdint>
#include <cstddef>

#define NTOK 4096
#define DDIM 1024

// ---------------------------------------------------------------------------
// Scratch (allocation-free)
// ---------------------------------------------------------------------------
__device__ __half g_Xh[(size_t)NTOK * DDIM];        // x   fp16
__device__ __half g_Wqh[(size_t)DDIM * DDIM];
__device__ __half g_Wkh[(size_t)DDIM * DDIM];
__device__ __half g_Wvh[(size_t)DDIM * DDIM];
__device__ __half g_Qh[(size_t)NTOK * DDIM];        // Q   fp16
__device__ __half g_Kh[(size_t)NTOK * DDIM];        // K   fp16
__device__ __half g_Vth[(size_t)DDIM * NTOK];       // V^T fp16
__device__ float  g_S[(size_t)NTOK * NTOK];         // scores fp32
__device__ __half g_Ph[(size_t)NTOK * NTOK];        // probs fp16

// ---------------------------------------------------------------------------
// Helpers
// ---------------------------------------------------------------------------
__device__ __forceinline__ void cp16(uint32_t dst, const void* src) {
    asm volatile("cp.async.cg.shared.global [%0], [%1], 16;" :: "r"(dst), "l"(src) : "memory");
}
#define CP_COMMIT()  asm volatile("cp.async.commit_group;" ::: "memory")
#define CP_WAIT(n)   asm volatile("cp.async.wait_group %0;" :: "n"(n) : "memory")

__device__ __forceinline__ uint32_t smem_u32(const void* p) {
    uint32_t a;
    asm("{ .reg .u64 t; cvta.to.shared.u64 t, %1; cvt.u32.u64 %0, t; }" : "=r"(a) : "l"(p));
    return a;
}
__device__ __forceinline__ void mma_f16(float c[4], const uint32_t a[4], const uint32_t* b) {
    asm volatile(
        "mma.sync.aligned.m16n8k16.row.col.f32.f16.f16.f32 "
        "{%0,%1,%2,%3}, {%4,%5,%6,%7}, {%8,%9}, {%0,%1,%2,%3};"
        : "+f"(c[0]), "+f"(c[1]), "+f"(c[2]), "+f"(c[3])
        : "r"(a[0]), "r"(a[1]), "r"(a[2]), "r"(a[3]), "r"(b[0]), "r"(b[1]));
}
#define LDSM_X4(r, addr) \
    asm volatile("ldmatrix.sync.aligned.m8n8.x4.shared.b16 {%0,%1,%2,%3}, [%4];" \
        : "=r"((r)[0]), "=r"((r)[1]), "=r"((r)[2]), "=r"((r)[3]) : "r"(addr))

// ---------------------------------------------------------------------------
// fp16 mma.sync NT-GEMM: C[M,N] = scale*(A @ B^T) + bias
//   A [M,K] fp16 row-major, B [N,K] fp16 row-major. M,N%128==0, K%32==0.
//   bias_mode: 0 = none, 1 = per-column bias[c], 2 = per-row bias[r]
//   out_half:  1 -> C is __half*, else float*
//
// 256 threads (8 warps, 2x4 grid, 64x32 warp tile, m16n8k16 frags, fp32 accum).
// 4-stage cp.async pipeline (81.9 KB smem -> 2 CTAs/SM).
// Tiles [128][40] fp16 (80B row stride): LDSM phase granules (5r mod 8) all
// distinct -> conflict-free; per-iter smem traffic halved vs tf32 path.
// ---------------------------------------------------------------------------
#define STAGES 4
#define BK 32
#define TW 40                                    // padded row stride (halfs)
#define TILE_HALFS (128 * TW)                    // 5120 halfs per operand tile
#define TILE_BYTES (TILE_HALFS * 2)              // 10240 B
#define STAGE_BYTES (2 * TILE_BYTES)             // 20480 B
#define GEMM_SMEM (STAGES * STAGE_BYTES)         // 81920 B

__global__ void __launch_bounds__(256, 2)
hgemm_nt(const __half* __restrict__ A, const __half* __restrict__ B,
         const float* __restrict__ bias, void* __restrict__ Cv,
         int M, int N, int K, float scale, int bias_mode, int out_half)
{
    extern __shared__ char smem[];
    const uint32_t sb = smem_u32(smem);

    const int tid  = threadIdx.x;
    const int wid  = tid >> 5;
    const int lane = tid & 31;
    const int r4   = lane >> 2;
    const int t4   = lane & 3;

    const int warpRow = (wid & 1) * 64;   // 2 warps over M
    const int warpCol = (wid >> 1) * 32;  // 4 warps over N

    const int row0 = blockIdx.y * 128;
    const int col0 = blockIdx.x * 128;
    const int NITER = K / BK;

    // ldmatrix per-lane base addresses (stage 0, kstep 0), byte offsets
    const uint32_t aAddr0 = sb +
        (uint32_t)(((warpRow + (lane & 15)) * TW + (lane >> 4) * 8) * 2);
    const uint32_t bAddr0 = sb + TILE_BYTES +
        (uint32_t)(((warpCol + (lane & 7) + ((lane >> 4) & 1) * 8) * TW + ((lane >> 3) & 1) * 8) * 2);

    // loader: thread t -> row t>>1, 32B half-row (t&1), 2 cp16 per operand
    const int lrow = tid >> 1;
    const int lh   = (tid & 1) * 16;     // half offset within row
    const __half* Ag = A + (size_t)(row0 + lrow) * K + lh;
    const __half* Bg = B + (size_t)(col0 + lrow) * K + lh;
    const uint32_t dstA = sb + (uint32_t)(lrow * TW + lh) * 2u;
    const uint32_t dstB = dstA + TILE_BYTES;

    float acc[4][4][4];
#pragma unroll
    for (int i = 0; i < 4; i++)
#pragma unroll
        for (int j = 0; j < 4; j++)
#pragma unroll
            for (int q = 0; q < 4; q++) acc[i][j][q] = 0.f;

    // --- prologue: fill STAGES-1 stages ---
#pragma unroll
    for (int p = 0; p < STAGES - 1; p++) {
        const uint32_t so = (uint32_t)(p * STAGE_BYTES);
        const __half* a = Ag + (size_t)p * BK;
        const __half* b = Bg + (size_t)p * BK;
        cp16(dstA + so,       a);
        cp16(dstA + so + 16u, a + 8);
        cp16(dstB + so,       b);
        cp16(dstB + so + 16u, b + 8);
        CP_COMMIT();
    }

    // --- mainloop ---
    for (int j = 0; j < NITER; j++) {
        CP_WAIT(STAGES - 2);
        __syncthreads();

        const int jn = j + STAGES - 1;
        if (jn < NITER) {
            const uint32_t so = (uint32_t)((jn % STAGES) * STAGE_BYTES);
            const __half* a = Ag + (size_t)jn * BK;
            const __half* b = Bg + (size_t)jn * BK;
            cp16(dstA + so,       a);
            cp16(dstA + so + 16u, a + 8);
            cp16(dstB + so,       b);
            cp16(dstB + so + 16u, b + 8);
            CP_COMMIT();
        }

        const uint32_t so = (uint32_t)((j % STAGES) * STAGE_BYTES);

#pragma unroll
        for (int ks = 0; ks < 2; ks++) {            // two k16 steps per BK=32
            const uint32_t ko = (uint32_t)ks * 32u; // 16 halfs = 32 B
            uint32_t afr[4][4], bfr[2][4];
#pragma unroll
            for (int mf = 0; mf < 4; mf++)
                LDSM_X4(afr[mf], aAddr0 + so + (uint32_t)(mf * 16 * TW * 2) + ko);
#pragma unroll
            for (int p = 0; p < 2; p++)
                LDSM_X4(bfr[p], bAddr0 + so + (uint32_t)(p * 16 * TW * 2) + ko);
#pragma unroll
            for (int mf = 0; mf < 4; mf++)
#pragma unroll
                for (int nf = 0; nf < 4; nf++)
                    mma_f16(acc[mf][nf], afr[mf], &bfr[nf >> 1][(nf & 1) * 2]);
        }
    }

    // --- epilogue ---
#pragma unroll
    for (int mf = 0; mf < 4; mf++) {
#pragma unroll
        for (int half = 0; half < 2; half++) {
            const int r = row0 + warpRow + mf * 16 + r4 + half * 8;
            const float brow = (bias_mode == 2) ? bias[r] : 0.f;
#pragma unroll
            for (int nf = 0; nf < 4; nf++) {
                const int c = warpCol + nf * 8 + 2 * t4;
                float vx = acc[mf][nf][half * 2 + 0] * scale;
                float vy = acc[mf][nf][half * 2 + 1] * scale;
                if (bias_mode == 1) {
                    vx += bias[col0 + c];
                    vy += bias[col0 + c + 1];
                } else {
                    vx += brow;
                    vy += brow;
                }
                if (out_half) {
                    __half2* Crow = (__half2*)((__half*)Cv + (size_t)r * N + col0 + c);
                    *Crow = __floats2half2_rn(vx, vy);
                } else {
                    float2* Crow = (float2*)((float*)Cv + (size_t)r * N + col0 + c);
                    *Crow = make_float2(vx, vy);
                }
            }
        }
    }
}

// ---------------------------------------------------------------------------
// fp32 -> fp16 conversion (float4 -> half2x2), grid-stride
// ---------------------------------------------------------------------------
__global__ void __launch_bounds__(256) f32_to_f16(
    const float* __restrict__ src, __half* __restrict__ dst, int n4)
{
    const float4* s4 = (const float4*)src;
    for (int i = blockIdx.x * blockDim.x + threadIdx.x; i < n4; i += gridDim.x * blockDim.x) {
        float4 v = s4[i];
        __half2 lo = __floats2half2_rn(v.x, v.y);
        __half2 hi = __floats2half2_rn(v.z, v.w);
        *(uint2*)(dst + (size_t)i * 4) = make_uint2(
            *(uint32_t*)&lo, *(uint32_t*)&hi);
    }
}

// ---------------------------------------------------------------------------
// Row softmax: S (fp32) -> P (fp16)
// ---------------------------------------------------------------------------
__global__ void __launch_bounds__(256) softmax_rows(
    const float* __restrict__ S, __half* __restrict__ P, int n)
{
    __shared__ float rowbuf[NTOK];
    __shared__ float red[256];

    const int tid = threadIdx.x;
    const float* Sr = S + (size_t)blockIdx.x * n;
    __half* Pr = P + (size_t)blockIdx.x * n;

    float m = -1e30f;
    for (int i = tid; i < n; i += 256) {
        float v = Sr[i];
        rowbuf[i] = v;
        m = fmaxf(m, v);
    }
    red[tid] = m;
    __syncthreads();
#pragma unroll
    for (int s = 128; s > 0; s >>= 1) {
        if (tid < s) red[tid] = fmaxf(red[tid], red[tid + s]);
        __syncthreads();
    }
    m = red[0];
    __syncthreads();

    float sum = 0.f;
    for (int i = tid; i < n; i += 256) {
        float e = __expf(rowbuf[i] - m);
        rowbuf[i] = e;
        sum += e;
    }
    red[tid] = sum;
    __syncthreads();
#pragma unroll
    for (int s = 128; s > 0; s >>= 1) {
        if (tid < s) red[tid] += red[tid + s];
        __syncthreads();
    }
    const float inv = 1.f / red[0];
    __syncthreads();

    for (int i = tid; i < n; i += 256)
        Pr[i] = __float2half_rn(rowbuf[i] * inv);
}

// ---------------------------------------------------------------------------
// Launch graph:
//   Xh,Wh = fp16(x, Wq, Wk, Wv)
//   Qh  = Xh @ Wqh^T + bq    (col bias, fp16 out)
//   Kh  = Xh @ Wkh^T + bk    (col bias, fp16 out)
//   Vth = Wvh @ Xh^T + bv    (row bias, fp16 out)  -> V^T [1024,4096]
//   S   = (Qh @ Kh^T) / 32   (fp32 out)
//   Ph  = softmax_rows(S)    (fp16 out)
//   out = Ph @ Vth^T         (fp32 out)
// ---------------------------------------------------------------------------
extern "C" void kernel_launch(void* const* d_in, const int* in_sizes, int n_in,
                              void* d_out, int out_size)
{
    const float* x  = (const float*)d_in[0];
    const float* Wq = (const float*)d_in[1];
    const float* bq = (const float*)d_in[2];
    const float* Wk = (const float*)d_in[3];
    const float* bk = (const float*)d_in[4];
    const float* Wv = (const float*)d_in[5];
    const float* bv = (const float*)d_in[6];
    float* out = (float*)d_out;

    __half *Xh, *Wqh, *Wkh, *Wvh, *Qh, *Kh, *Vth, *Ph;
    float *S;
    cudaGetSymbolAddress((void**)&Xh,  g_Xh);
    cudaGetSymbolAddress((void**)&Wqh, g_Wqh);
    cudaGetSymbolAddress((void**)&Wkh, g_Wkh);
    cudaGetSymbolAddress((void**)&Wvh, g_Wvh);
    cudaGetSymbolAddress((void**)&Qh,  g_Qh);
    cudaGetSymbolAddress((void**)&Kh,  g_Kh);
    cudaGetSymbolAddress((void**)&Vth, g_Vth);
    cudaGetSymbolAddress((void**)&S,   g_S);
    cudaGetSymbolAddress((void**)&Ph,  g_Ph);

    cudaFuncSetAttribute(hgemm_nt, cudaFuncAttributeMaxDynamicSharedMemorySize, GEMM_SMEM);

    dim3 blk(256);

    // fp16 conversions
    f32_to_f16<<<1024, blk>>>(x,  Xh,  NTOK * DDIM / 4);
    f32_to_f16<<<512,  blk>>>(Wq, Wqh, DDIM * DDIM / 4);
    f32_to_f16<<<512,  blk>>>(Wk, Wkh, DDIM * DDIM / 4);
    f32_to_f16<<<512,  blk>>>(Wv, Wvh, DDIM * DDIM / 4);

    // Projections (fp16 outputs)
    hgemm_nt<<<dim3(DDIM / 128, NTOK / 128), blk, GEMM_SMEM>>>(Xh, Wqh, bq, Qh,  NTOK, DDIM, DDIM, 1.0f, 1, 1);
    hgemm_nt<<<dim3(DDIM / 128, NTOK / 128), blk, GEMM_SMEM>>>(Xh, Wkh, bk, Kh,  NTOK, DDIM, DDIM, 1.0f, 1, 1);
    hgemm_nt<<<dim3(NTOK / 128, DDIM / 128), blk, GEMM_SMEM>>>(Wvh, Xh, bv, Vth, DDIM, NTOK, DDIM, 1.0f, 2, 1);

    // Scores (fp32 out)
    hgemm_nt<<<dim3(NTOK / 128, NTOK / 128), blk, GEMM_SMEM>>>(Qh, Kh, nullptr, S, NTOK, NTOK, DDIM, 0.03125f, 0, 0);

    // Softmax (fp16 out)
    softmax_rows<<<NTOK, blk>>>(S, Ph, NTOK);

    // Output (fp32)
    hgemm_nt<<<dim3(DDIM / 128, NTOK / 128), blk, GEMM_SMEM>>>(Ph, Vth, nullptr, out, NTOK, DDIM, NTOK, 1.0f, 0, 0);
}